// round 4
// baseline (speedup 1.0000x reference)
#include <cuda_runtime.h>
#include <cuda_bf16.h>
#include <cstdint>
#include <math.h>

#define BDIM   16384
#define IN_DIM 4096
#define H1D    128
#define H2D    64
#define LAT    32
#define NREPS  3
#define SROW   80        // padded smem row stride (bytes) for 32 bf16 = 64B data

// ---------------------------------------------------------------------------
// Scratch (__device__ globals: allocation-free rule)
// ---------------------------------------------------------------------------
__device__ float g_h1[(size_t)BDIM * H1D];                            // 8 MB
__device__ __align__(16) __nv_bfloat16 g_q_h[(size_t)BDIM * LAT];
__device__ __align__(16) __nv_bfloat16 g_q_l[(size_t)BDIM * LAT];
__device__ __align__(16) __nv_bfloat16 g_W1t_h[(size_t)H1D * IN_DIM]; // W1^T [n][k]
__device__ __align__(16) __nv_bfloat16 g_W1t_l[(size_t)H1D * IN_DIM];
__device__ __align__(16) __nv_bfloat16 g_Wdt_h[(size_t)IN_DIM * LAT]; // Wd^T [n][k]
__device__ __align__(16) __nv_bfloat16 g_Wdt_l[(size_t)IN_DIM * LAT];

// ---------------------------------------------------------------------------
// Helpers (baseline PTX only: ldmatrix + mma.sync, sm_80-compatible)
// ---------------------------------------------------------------------------
__device__ __forceinline__ uint32_t smem_u32(const void* p) {
    uint32_t a;
    asm("{ .reg .u64 t; cvta.to.shared.u64 t, %1; cvt.u32.u64 %0, t; }" : "=r"(a) : "l"(p));
    return a;
}
__device__ __forceinline__ void ldsm_x4(uint32_t* r, uint32_t addr) {
    asm volatile("ldmatrix.sync.aligned.m8n8.x4.shared.b16 {%0,%1,%2,%3}, [%4];"
                 : "=r"(r[0]), "=r"(r[1]), "=r"(r[2]), "=r"(r[3]) : "r"(addr));
}
__device__ __forceinline__ void ldsm_x2(uint32_t* r, uint32_t addr) {
    asm volatile("ldmatrix.sync.aligned.m8n8.x2.shared.b16 {%0,%1}, [%2];"
                 : "=r"(r[0]), "=r"(r[1]) : "r"(addr));
}
__device__ __forceinline__ void mma16816(float* c, const uint32_t* a, const uint32_t* b) {
    asm volatile("mma.sync.aligned.m16n8k16.row.col.f32.bf16.bf16.f32 "
                 "{%0,%1,%2,%3}, {%4,%5,%6,%7}, {%8,%9}, {%0,%1,%2,%3};"
                 : "+f"(c[0]), "+f"(c[1]), "+f"(c[2]), "+f"(c[3])
                 : "r"(a[0]), "r"(a[1]), "r"(a[2]), "r"(a[3]), "r"(b[0]), "r"(b[1]));
}
__device__ __forceinline__ uint32_t pack_bf16x2(__nv_bfloat16 a, __nv_bfloat16 b) {
    return (uint32_t)__bfloat16_as_ushort(a) | ((uint32_t)__bfloat16_as_ushort(b) << 16);
}
__device__ __forceinline__ void split_bf16(float v, __nv_bfloat16& hi, __nv_bfloat16& lo) {
    hi = __float2bfloat16_rn(v);
    lo = __float2bfloat16_rn(v - __bfloat162float(hi));
}

// ---------------------------------------------------------------------------
// Prep: W1 [4096,128] -> W1^T hi/lo bf16 [128,4096]; Wd [32,4096] -> Wd^T [4096,32]
// ---------------------------------------------------------------------------
__global__ void k_tr_W1(const float* __restrict__ W1) {
    __shared__ float t[32][33];
    const int k0 = blockIdx.x * 32, n0 = blockIdx.y * 32;
    const int tx = threadIdx.x, ty = threadIdx.y;   // (32, 8)
    #pragma unroll
    for (int i = 0; i < 4; i++)
        t[ty + 8 * i][tx] = W1[(size_t)(k0 + ty + 8 * i) * H1D + n0 + tx];
    __syncthreads();
    #pragma unroll
    for (int i = 0; i < 4; i++) {
        const int n = n0 + ty + 8 * i, k = k0 + tx;
        __nv_bfloat16 h, l;
        split_bf16(t[tx][ty + 8 * i], h, l);
        g_W1t_h[(size_t)n * IN_DIM + k] = h;
        g_W1t_l[(size_t)n * IN_DIM + k] = l;
    }
}
__global__ void k_tr_Wd(const float* __restrict__ Wd) {
    __shared__ float t[32][33];
    const int n0 = blockIdx.x * 32;
    const int tx = threadIdx.x, ty = threadIdx.y;   // (32, 8)
    #pragma unroll
    for (int i = 0; i < 4; i++)
        t[ty + 8 * i][tx] = Wd[(size_t)(ty + 8 * i) * IN_DIM + n0 + tx];
    __syncthreads();
    #pragma unroll
    for (int i = 0; i < 4; i++) {
        const int n = n0 + ty + 8 * i, k = tx;
        __nv_bfloat16 h, l;
        split_bf16(t[tx][ty + 8 * i], h, l);
        g_Wdt_h[(size_t)n * LAT + k] = h;
        g_Wdt_l[(size_t)n * LAT + k] = l;
    }
}

// ---------------------------------------------------------------------------
// GEMM1 (mma.sync): h1 = relu(x @ W1 + b1)
// CTA tile 128x128, BK=32, 8 warps (2x4), warp tile 64x32.
// Double-buffered smem (2 x 40 KB), one __syncthreads per K-iter.
// ---------------------------------------------------------------------------
#define G1_STAGE (4 * 128 * SROW)          // 40960
#define G1_SMEM  (2 * G1_STAGE)            // 81920
__global__ __launch_bounds__(256) void k_gemm1_mma(const float* __restrict__ x,
                                                   const float* __restrict__ b1)
{
    extern __shared__ __align__(128) char sm[];

    const int tid  = threadIdx.x;
    const int lane = tid & 31, wid = tid >> 5;
    const int wm = wid >> 2, wn = wid & 3;         // warp grid 2(m) x 4(n)
    const int r = tid >> 1, h = tid & 1;           // load role: row, k-half
    const int row0 = blockIdx.x * 128;

    float acc[4][4][4];
    #pragma unroll
    for (int im = 0; im < 4; im++)
        #pragma unroll
        for (int in = 0; in < 4; in++)
            #pragma unroll
            for (int j = 0; j < 4; j++) acc[im][in][j] = 0.f;

    const float*         xp  = &x[(size_t)(row0 + r) * IN_DIM + h * 16];
    const __nv_bfloat16* wph = &g_W1t_h[(size_t)r * IN_DIM + h * 16];
    const __nv_bfloat16* wpl = &g_W1t_l[(size_t)r * IN_DIM + h * 16];

    const uint32_t sts = (uint32_t)(r * SROW + h * 32);
    const uint32_t akb = (uint32_t)((lane >> 4) * 16 + (lane & 15) * SROW);
    const uint32_t bkb = (uint32_t)(((lane >> 3) & 1) * 16 + (lane & 7) * SROW);
    const uint32_t amo = (uint32_t)((wm * 64) * SROW) + akb;
    const uint32_t bno = (uint32_t)((wn * 32) * SROW) + bkb;

    // ---- prologue: tile 0 -> regs -> buf0 ----
    float4 xa[4]; uint4 wbh[2], wbl[2];
    #pragma unroll
    for (int j = 0; j < 4; j++) xa[j] = *(const float4*)(xp + j * 4);
    wbh[0] = *(const uint4*)wph; wbh[1] = *(const uint4*)(wph + 8);
    wbl[0] = *(const uint4*)wpl; wbl[1] = *(const uint4*)(wpl + 8);
    {
        char* sb = sm;
        uint32_t hh[8], ll[8];
        #pragma unroll
        for (int j = 0; j < 4; j++) {
            __nv_bfloat16 h0, l0, h1_, l1, h2, l2, h3, l3;
            split_bf16(xa[j].x, h0, l0); split_bf16(xa[j].y, h1_, l1);
            split_bf16(xa[j].z, h2, l2); split_bf16(xa[j].w, h3, l3);
            hh[2 * j] = pack_bf16x2(h0, h1_); hh[2 * j + 1] = pack_bf16x2(h2, h3);
            ll[2 * j] = pack_bf16x2(l0, l1);  ll[2 * j + 1] = pack_bf16x2(l2, l3);
        }
        *(uint4*)(sb + sts)                  = make_uint4(hh[0], hh[1], hh[2], hh[3]);
        *(uint4*)(sb + sts + 16)             = make_uint4(hh[4], hh[5], hh[6], hh[7]);
        *(uint4*)(sb + 10240 + sts)          = make_uint4(ll[0], ll[1], ll[2], ll[3]);
        *(uint4*)(sb + 10240 + sts + 16)     = make_uint4(ll[4], ll[5], ll[6], ll[7]);
        *(uint4*)(sb + 20480 + sts)          = wbh[0];
        *(uint4*)(sb + 20480 + sts + 16)     = wbh[1];
        *(uint4*)(sb + 30720 + sts)          = wbl[0];
        *(uint4*)(sb + 30720 + sts + 16)     = wbl[1];
    }
    __syncthreads();

    for (int i = 0; i < IN_DIM / 32; ++i) {
        const int s = i & 1;
        char* cb = sm + s * G1_STAGE;                 // compute buffer
        char* nb = sm + (s ^ 1) * G1_STAGE;           // next (store) buffer
        const uint32_t uAh = smem_u32(cb);
        const uint32_t uAl = uAh + 10240;
        const uint32_t uBh = uAh + 20480;
        const uint32_t uBl = uAh + 30720;

        // prefetch next tile (long-latency first)
        const bool more = (i < IN_DIM / 32 - 1);
        if (more) {
            const int off = (i + 1) * 32;
            #pragma unroll
            for (int j = 0; j < 4; j++) xa[j] = *(const float4*)(xp + off + j * 4);
            wbh[0] = *(const uint4*)(wph + off); wbh[1] = *(const uint4*)(wph + off + 8);
            wbl[0] = *(const uint4*)(wpl + off); wbl[1] = *(const uint4*)(wpl + off + 8);
        }

        // MMA over current buffer
        #pragma unroll
        for (int ks = 0; ks < 2; ks++) {
            uint32_t ah[4][4], al[4][4], bh[4][2], bl[4][2];
            #pragma unroll
            for (int im = 0; im < 4; im++) {
                const uint32_t mo = amo + (uint32_t)(im * 16 * SROW) + (uint32_t)(ks * 32);
                ldsm_x4(ah[im], uAh + mo);
                ldsm_x4(al[im], uAl + mo);
            }
            #pragma unroll
            for (int in = 0; in < 4; in++) {
                const uint32_t no = bno + (uint32_t)(in * 8 * SROW) + (uint32_t)(ks * 32);
                ldsm_x2(bh[in], uBh + no);
                ldsm_x2(bl[in], uBl + no);
            }
            #pragma unroll
            for (int im = 0; im < 4; im++)
                #pragma unroll
                for (int in = 0; in < 4; in++) {
                    mma16816(acc[im][in], ah[im], bh[in]);
                    mma16816(acc[im][in], ah[im], bl[in]);
                    mma16816(acc[im][in], al[im], bh[in]);
                }
        }

        // convert + STS next tile into other buffer
        if (more) {
            uint32_t hh[8], ll[8];
            #pragma unroll
            for (int j = 0; j < 4; j++) {
                __nv_bfloat16 h0, l0, h1_, l1, h2, l2, h3, l3;
                split_bf16(xa[j].x, h0, l0); split_bf16(xa[j].y, h1_, l1);
                split_bf16(xa[j].z, h2, l2); split_bf16(xa[j].w, h3, l3);
                hh[2 * j] = pack_bf16x2(h0, h1_); hh[2 * j + 1] = pack_bf16x2(h2, h3);
                ll[2 * j] = pack_bf16x2(l0, l1);  ll[2 * j + 1] = pack_bf16x2(l2, l3);
            }
            *(uint4*)(nb + sts)              = make_uint4(hh[0], hh[1], hh[2], hh[3]);
            *(uint4*)(nb + sts + 16)         = make_uint4(hh[4], hh[5], hh[6], hh[7]);
            *(uint4*)(nb + 10240 + sts)      = make_uint4(ll[0], ll[1], ll[2], ll[3]);
            *(uint4*)(nb + 10240 + sts + 16) = make_uint4(ll[4], ll[5], ll[6], ll[7]);
            *(uint4*)(nb + 20480 + sts)      = wbh[0];
            *(uint4*)(nb + 20480 + sts + 16) = wbh[1];
            *(uint4*)(nb + 30720 + sts)      = wbl[0];
            *(uint4*)(nb + 30720 + sts + 16) = wbl[1];
        }
        __syncthreads();
    }

    // epilogue: bias + relu -> g_h1
    #pragma unroll
    for (int im = 0; im < 4; im++) {
        const int rowa = row0 + wm * 64 + im * 16 + (lane >> 2);
        #pragma unroll
        for (int in = 0; in < 4; in++) {
            const int col = wn * 32 + in * 8 + 2 * (lane & 3);
            const float bb0 = b1[col], bb1 = b1[col + 1];
            float2 v0 = make_float2(fmaxf(acc[im][in][0] + bb0, 0.f),
                                    fmaxf(acc[im][in][1] + bb1, 0.f));
            float2 v1 = make_float2(fmaxf(acc[im][in][2] + bb0, 0.f),
                                    fmaxf(acc[im][in][3] + bb1, 0.f));
            *(float2*)&g_h1[(size_t)rowa * H1D + col]       = v0;
            *(float2*)&g_h1[(size_t)(rowa + 8) * H1D + col] = v1;
        }
    }
}

// ---------------------------------------------------------------------------
// Head v2: h1 -> h2 -> z -> q = cos(z+off) as bf16 hi/lo.
// 32 rows/block, 128 threads (4 threads per row).  W2/W3 via broadcast
// float4 LDG (L1-resident).  h2 stays in registers; stage-2 partials reduced
// with shfl_xor across the 4 lanes sharing a row.
// ---------------------------------------------------------------------------
__global__ __launch_bounds__(128) void k_head(const float* __restrict__ W2,
                                              const float* __restrict__ b2,
                                              const float* __restrict__ W3,
                                              const float* __restrict__ b3,
                                              const float* __restrict__ qparams)
{
    __shared__ float h1s[32][129];

    const int row0 = blockIdx.x * 32;
    const int tid  = threadIdx.x;

    // stage h1 tile (32 x 128)
    #pragma unroll
    for (int i = 0; i < 8; i++) {
        int f = tid + 128 * i;
        int r_ = f >> 5, c4 = (f & 31) << 2;
        float4 v = *(const float4*)&g_h1[(size_t)(row0 + r_) * H1D + c4];
        h1s[r_][c4 + 0] = v.x; h1s[r_][c4 + 1] = v.y;
        h1s[r_][c4 + 2] = v.z; h1s[r_][c4 + 3] = v.w;
    }
    __syncthreads();

    const int r  = tid >> 2;    // row 0..31
    const int jg = tid & 3;     // j-group

    // ---- stage 1: h2[jg*16 .. +16] = relu(h1 . W2 + b2) ----
    float acc[16];
    #pragma unroll
    for (int t = 0; t < 16; t++) acc[t] = b2[jg * 16 + t];

    #pragma unroll 4
    for (int k = 0; k < H1D; k++) {
        const float hv = h1s[r][k];
        const float4* wr = (const float4*)&W2[k * H2D + jg * 16];
        float4 w0 = wr[0], w1 = wr[1], w2 = wr[2], w3v = wr[3];
        acc[0]  = fmaf(hv, w0.x,  acc[0]);  acc[1]  = fmaf(hv, w0.y,  acc[1]);
        acc[2]  = fmaf(hv, w0.z,  acc[2]);  acc[3]  = fmaf(hv, w0.w,  acc[3]);
        acc[4]  = fmaf(hv, w1.x,  acc[4]);  acc[5]  = fmaf(hv, w1.y,  acc[5]);
        acc[6]  = fmaf(hv, w1.z,  acc[6]);  acc[7]  = fmaf(hv, w1.w,  acc[7]);
        acc[8]  = fmaf(hv, w2.x,  acc[8]);  acc[9]  = fmaf(hv, w2.y,  acc[9]);
        acc[10] = fmaf(hv, w2.z,  acc[10]); acc[11] = fmaf(hv, w2.w,  acc[11]);
        acc[12] = fmaf(hv, w3v.x, acc[12]); acc[13] = fmaf(hv, w3v.y, acc[13]);
        acc[14] = fmaf(hv, w3v.z, acc[14]); acc[15] = fmaf(hv, w3v.w, acc[15]);
    }
    #pragma unroll
    for (int t = 0; t < 16; t++) acc[t] = fmaxf(acc[t], 0.f);

    // ---- stage 2: partial z over this thread's 16 k2-values ----
    float zp[32];
    #pragma unroll
    for (int j = 0; j < 32; j++) zp[j] = 0.f;

    #pragma unroll
    for (int t = 0; t < 16; t++) {
        const int k2 = jg * 16 + t;
        const float hv = acc[t];
        const float4* wr = (const float4*)&W3[k2 * LAT];
        #pragma unroll
        for (int j4 = 0; j4 < 8; j4++) {
            float4 w = wr[j4];
            zp[j4 * 4 + 0] = fmaf(hv, w.x, zp[j4 * 4 + 0]);
            zp[j4 * 4 + 1] = fmaf(hv, w.y, zp[j4 * 4 + 1]);
            zp[j4 * 4 + 2] = fmaf(hv, w.z, zp[j4 * 4 + 2]);
            zp[j4 * 4 + 3] = fmaf(hv, w.w, zp[j4 * 4 + 3]);
        }
    }
    // reduce across the 4 lanes of this row (lanes 4m..4m+3)
    #pragma unroll
    for (int j = 0; j < 32; j++) {
        zp[j] += __shfl_xor_sync(0xffffffffu, zp[j], 1);
        zp[j] += __shfl_xor_sync(0xffffffffu, zp[j], 2);
    }

    // ---- finalize: this thread owns j = jg*8 .. +8 ----
    #pragma unroll
    for (int jj = 0; jj < 8; jj++) {
        const int j = jg * 8 + jj;
        float off = 0.f;
        #pragma unroll
        for (int rep = 0; rep < 2 * NREPS; rep++)
            off += qparams[rep * LAT + j];
        const float qv = cosf(zp[j] + b3[j] + off);
        __nv_bfloat16 hh, ll;
        split_bf16(qv, hh, ll);
        g_q_h[(size_t)(row0 + r) * LAT + j] = hh;
        g_q_l[(size_t)(row0 + r) * LAT + j] = ll;
    }
}

// ---------------------------------------------------------------------------
// GEMM2 (mma.sync): out = q @ Wd + bd.  CTA tile 128x128, K=32 single shot.
// ---------------------------------------------------------------------------
__global__ __launch_bounds__(256) void k_gemm2_mma(const float* __restrict__ bd,
                                                   float* __restrict__ out)
{
    __shared__ __align__(128) char sm[4 * 128 * SROW];
    char* sQh = sm;
    char* sQl = sm + 128 * SROW;
    char* sWh = sm + 2 * 128 * SROW;
    char* sWl = sm + 3 * 128 * SROW;
    const uint32_t uQh = smem_u32(sQh), uQl = smem_u32(sQl);
    const uint32_t uWh = smem_u32(sWh), uWl = smem_u32(sWl);

    const int tid  = threadIdx.x;
    const int lane = tid & 31, wid = tid >> 5;
    const int wm = wid >> 2, wn = wid & 3;
    const int r = tid >> 1, h = tid & 1;
    const int n0 = blockIdx.x * 128;
    const int m0 = blockIdx.y * 128;

    const uint32_t sts = (uint32_t)(r * SROW + h * 32);
    {
        const __nv_bfloat16* qh = &g_q_h[(size_t)(m0 + r) * LAT + h * 16];
        const __nv_bfloat16* ql = &g_q_l[(size_t)(m0 + r) * LAT + h * 16];
        const __nv_bfloat16* wh = &g_Wdt_h[(size_t)(n0 + r) * LAT + h * 16];
        const __nv_bfloat16* wl = &g_Wdt_l[(size_t)(n0 + r) * LAT + h * 16];
        *(uint4*)(sQh + sts)      = *(const uint4*)qh;
        *(uint4*)(sQh + sts + 16) = *(const uint4*)(qh + 8);
        *(uint4*)(sQl + sts)      = *(const uint4*)ql;
        *(uint4*)(sQl + sts + 16) = *(const uint4*)(ql + 8);
        *(uint4*)(sWh + sts)      = *(const uint4*)wh;
        *(uint4*)(sWh + sts + 16) = *(const uint4*)(wh + 8);
        *(uint4*)(sWl + sts)      = *(const uint4*)wl;
        *(uint4*)(sWl + sts + 16) = *(const uint4*)(wl + 8);
    }
    __syncthreads();

    float acc[4][4][4];
    #pragma unroll
    for (int im = 0; im < 4; im++)
        #pragma unroll
        for (int in = 0; in < 4; in++)
            #pragma unroll
            for (int j = 0; j < 4; j++) acc[im][in][j] = 0.f;

    #pragma unroll
    for (int ks = 0; ks < 2; ks++) {
        uint32_t ah[4][4], al[4][4], bh[4][2], bl[4][2];
        const uint32_t akb = (uint32_t)(ks * 32 + (lane >> 4) * 16 + (lane & 15) * SROW);
        #pragma unroll
        for (int im = 0; im < 4; im++) {
            const uint32_t mo = (uint32_t)((wm * 64 + im * 16) * SROW) + akb;
            ldsm_x4(ah[im], uQh + mo);
            ldsm_x4(al[im], uQl + mo);
        }
        const uint32_t bkb = (uint32_t)(ks * 32 + ((lane >> 3) & 1) * 16 + (lane & 7) * SROW);
        #pragma unroll
        for (int in = 0; in < 4; in++) {
            const uint32_t no = (uint32_t)((wn * 32 + in * 8) * SROW) + bkb;
            ldsm_x2(bh[in], uWh + no);
            ldsm_x2(bl[in], uWl + no);
        }
        #pragma unroll
        for (int im = 0; im < 4; im++)
            #pragma unroll
            for (int in = 0; in < 4; in++) {
                mma16816(acc[im][in], ah[im], bh[in]);
                mma16816(acc[im][in], ah[im], bl[in]);
                mma16816(acc[im][in], al[im], bh[in]);
            }
    }

    // epilogue: + bd -> out
    #pragma unroll
    for (int im = 0; im < 4; im++) {
        const int rowa = m0 + wm * 64 + im * 16 + (lane >> 2);
        #pragma unroll
        for (int in = 0; in < 4; in++) {
            const int col = n0 + wn * 32 + in * 8 + 2 * (lane & 3);
            const float bb0 = bd[col], bb1 = bd[col + 1];
            float2 v0 = make_float2(acc[im][in][0] + bb0, acc[im][in][1] + bb1);
            float2 v1 = make_float2(acc[im][in][2] + bb0, acc[im][in][3] + bb1);
            *(float2*)&out[(size_t)rowa * IN_DIM + col]       = v0;
            *(float2*)&out[(size_t)(rowa + 8) * IN_DIM + col] = v1;
        }
    }
}

// ---------------------------------------------------------------------------
extern "C" void kernel_launch(void* const* d_in, const int* in_sizes, int n_in,
                              void* d_out, int out_size)
{
    const float* x  = (const float*)d_in[0];
    const float* W1 = (const float*)d_in[1];
    const float* b1 = (const float*)d_in[2];
    const float* W2 = (const float*)d_in[3];
    const float* b2 = (const float*)d_in[4];
    const float* W3 = (const float*)d_in[5];
    const float* b3 = (const float*)d_in[6];
    const float* qp = (const float*)d_in[7];
    const float* Wd = (const float*)d_in[8];
    const float* bd = (const float*)d_in[9];
    float* out = (float*)d_out;

    cudaFuncSetAttribute(k_gemm1_mma, cudaFuncAttributeMaxDynamicSharedMemorySize, G1_SMEM);

    k_tr_W1<<<dim3(IN_DIM / 32, H1D / 32), dim3(32, 8)>>>(W1);
    k_tr_Wd<<<IN_DIM / 32, dim3(32, 8)>>>(Wd);
    k_gemm1_mma<<<BDIM / 128, 256, G1_SMEM>>>(x, b1);
    k_head<<<BDIM / 32, 128>>>(W2, b2, W3, b3, qp);
    k_gemm2_mma<<<dim3(IN_DIM / 128, BDIM / 128), 256>>>(bd, out);
}

// round 5
// speedup vs baseline: 1.2474x; 1.2474x over previous
#include <cuda_runtime.h>
#include <cuda_bf16.h>
#include <cstdint>
#include <math.h>

#define BDIM   16384
#define IN_DIM 4096
#define H1D    128
#define H2D    64
#define LAT    32
#define NREPS  3
#define SROW   80        // padded smem row stride (bytes) for 32 bf16 = 64B data

// ---------------------------------------------------------------------------
// Scratch (__device__ globals: allocation-free rule)
// ---------------------------------------------------------------------------
__device__ float g_h1[(size_t)BDIM * H1D];                            // 8 MB
__device__ __align__(16) __nv_bfloat16 g_q_h[(size_t)BDIM * LAT];
__device__ __align__(16) __nv_bfloat16 g_q_l[(size_t)BDIM * LAT];
__device__ __align__(16) __nv_bfloat16 g_W1t_h[(size_t)H1D * IN_DIM]; // W1^T [n][k]
__device__ __align__(16) __nv_bfloat16 g_W1t_l[(size_t)H1D * IN_DIM];
__device__ __align__(16) __nv_bfloat16 g_Wdt_h[(size_t)IN_DIM * LAT]; // Wd^T [n][k]
__device__ __align__(16) __nv_bfloat16 g_Wdt_l[(size_t)IN_DIM * LAT];

// ---------------------------------------------------------------------------
// Helpers (baseline PTX only: ldmatrix + mma.sync, sm_80-compatible)
// ---------------------------------------------------------------------------
__device__ __forceinline__ uint32_t smem_u32(const void* p) {
    uint32_t a;
    asm("{ .reg .u64 t; cvta.to.shared.u64 t, %1; cvt.u32.u64 %0, t; }" : "=r"(a) : "l"(p));
    return a;
}
__device__ __forceinline__ void ldsm_x4(uint32_t* r, uint32_t addr) {
    asm volatile("ldmatrix.sync.aligned.m8n8.x4.shared.b16 {%0,%1,%2,%3}, [%4];"
                 : "=r"(r[0]), "=r"(r[1]), "=r"(r[2]), "=r"(r[3]) : "r"(addr));
}
__device__ __forceinline__ void ldsm_x2(uint32_t* r, uint32_t addr) {
    asm volatile("ldmatrix.sync.aligned.m8n8.x2.shared.b16 {%0,%1}, [%2];"
                 : "=r"(r[0]), "=r"(r[1]) : "r"(addr));
}
__device__ __forceinline__ void mma16816(float* c, const uint32_t* a, const uint32_t* b) {
    asm volatile("mma.sync.aligned.m16n8k16.row.col.f32.bf16.bf16.f32 "
                 "{%0,%1,%2,%3}, {%4,%5,%6,%7}, {%8,%9}, {%0,%1,%2,%3};"
                 : "+f"(c[0]), "+f"(c[1]), "+f"(c[2]), "+f"(c[3])
                 : "r"(a[0]), "r"(a[1]), "r"(a[2]), "r"(a[3]), "r"(b[0]), "r"(b[1]));
}
__device__ __forceinline__ uint32_t pack_bf16x2(__nv_bfloat16 a, __nv_bfloat16 b) {
    return (uint32_t)__bfloat16_as_ushort(a) | ((uint32_t)__bfloat16_as_ushort(b) << 16);
}
__device__ __forceinline__ void split_bf16(float v, __nv_bfloat16& hi, __nv_bfloat16& lo) {
    hi = __float2bfloat16_rn(v);
    lo = __float2bfloat16_rn(v - __bfloat162float(hi));
}

// ---------------------------------------------------------------------------
// Prep: W1 [4096,128] -> W1^T hi/lo bf16 [128,4096]; Wd [32,4096] -> Wd^T [4096,32]
// ---------------------------------------------------------------------------
__global__ void k_tr_W1(const float* __restrict__ W1) {
    __shared__ float t[32][33];
    const int k0 = blockIdx.x * 32, n0 = blockIdx.y * 32;
    const int tx = threadIdx.x, ty = threadIdx.y;   // (32, 8)
    #pragma unroll
    for (int i = 0; i < 4; i++)
        t[ty + 8 * i][tx] = W1[(size_t)(k0 + ty + 8 * i) * H1D + n0 + tx];
    __syncthreads();
    #pragma unroll
    for (int i = 0; i < 4; i++) {
        const int n = n0 + ty + 8 * i, k = k0 + tx;
        __nv_bfloat16 h, l;
        split_bf16(t[tx][ty + 8 * i], h, l);
        g_W1t_h[(size_t)n * IN_DIM + k] = h;
        g_W1t_l[(size_t)n * IN_DIM + k] = l;
    }
}
__global__ void k_tr_Wd(const float* __restrict__ Wd) {
    __shared__ float t[32][33];
    const int n0 = blockIdx.x * 32;
    const int tx = threadIdx.x, ty = threadIdx.y;   // (32, 8)
    #pragma unroll
    for (int i = 0; i < 4; i++)
        t[ty + 8 * i][tx] = Wd[(size_t)(ty + 8 * i) * IN_DIM + n0 + tx];
    __syncthreads();
    #pragma unroll
    for (int i = 0; i < 4; i++) {
        const int n = n0 + ty + 8 * i, k = tx;
        __nv_bfloat16 h, l;
        split_bf16(t[tx][ty + 8 * i], h, l);
        g_Wdt_h[(size_t)n * LAT + k] = h;
        g_Wdt_l[(size_t)n * LAT + k] = l;
    }
}

// ---------------------------------------------------------------------------
// GEMM1 (mma.sync): h1 = relu(x @ W1 + b1)   [R3 single-buffer version]
// CTA tile 128x128, BK=32, 8 warps (2x4), warp tile 64x32.
// ---------------------------------------------------------------------------
__global__ __launch_bounds__(256) void k_gemm1_mma(const float* __restrict__ x,
                                                   const float* __restrict__ b1)
{
    __shared__ __align__(128) char sm[4 * 128 * SROW];   // Ah, Al, Bh, Bl (40 KB)
    char* sAh = sm;
    char* sAl = sm + 128 * SROW;
    char* sBh = sm + 2 * 128 * SROW;
    char* sBl = sm + 3 * 128 * SROW;
    const uint32_t uAh = smem_u32(sAh), uAl = smem_u32(sAl);
    const uint32_t uBh = smem_u32(sBh), uBl = smem_u32(sBl);

    const int tid  = threadIdx.x;
    const int lane = tid & 31, wid = tid >> 5;
    const int wm = wid >> 2, wn = wid & 3;         // warp grid 2(m) x 4(n)
    const int r = tid >> 1, h = tid & 1;           // load role: row, k-half
    const int row0 = blockIdx.x * 128;

    float acc[4][4][4];
    #pragma unroll
    for (int im = 0; im < 4; im++)
        #pragma unroll
        for (int in = 0; in < 4; in++)
            #pragma unroll
            for (int j = 0; j < 4; j++) acc[im][in][j] = 0.f;

    const float*         xp  = &x[(size_t)(row0 + r) * IN_DIM + h * 16];
    const __nv_bfloat16* wph = &g_W1t_h[(size_t)r * IN_DIM + h * 16];
    const __nv_bfloat16* wpl = &g_W1t_l[(size_t)r * IN_DIM + h * 16];

    // prefetch iter 0
    float4 xa[4]; uint4 wbh[2], wbl[2];
    #pragma unroll
    for (int j = 0; j < 4; j++) xa[j] = *(const float4*)(xp + j * 4);
    wbh[0] = *(const uint4*)wph; wbh[1] = *(const uint4*)(wph + 8);
    wbl[0] = *(const uint4*)wpl; wbl[1] = *(const uint4*)(wpl + 8);

    const uint32_t sts = (uint32_t)(r * SROW + h * 32);

    for (int i = 0; i < IN_DIM / 32; ++i) {
        // convert + STS of current tile
        uint32_t hh[8], ll[8];
        #pragma unroll
        for (int j = 0; j < 4; j++) {
            __nv_bfloat16 h0, l0, h1_, l1, h2, l2, h3, l3;
            split_bf16(xa[j].x, h0, l0); split_bf16(xa[j].y, h1_, l1);
            split_bf16(xa[j].z, h2, l2); split_bf16(xa[j].w, h3, l3);
            hh[2 * j]     = pack_bf16x2(h0, h1_); hh[2 * j + 1] = pack_bf16x2(h2, h3);
            ll[2 * j]     = pack_bf16x2(l0, l1);  ll[2 * j + 1] = pack_bf16x2(l2, l3);
        }
        *(uint4*)(sAh + sts)      = make_uint4(hh[0], hh[1], hh[2], hh[3]);
        *(uint4*)(sAh + sts + 16) = make_uint4(hh[4], hh[5], hh[6], hh[7]);
        *(uint4*)(sAl + sts)      = make_uint4(ll[0], ll[1], ll[2], ll[3]);
        *(uint4*)(sAl + sts + 16) = make_uint4(ll[4], ll[5], ll[6], ll[7]);
        *(uint4*)(sBh + sts)      = wbh[0];
        *(uint4*)(sBh + sts + 16) = wbh[1];
        *(uint4*)(sBl + sts)      = wbl[0];
        *(uint4*)(sBl + sts + 16) = wbl[1];
        __syncthreads();

        // prefetch next tile (overlaps with ldmatrix/mma below)
        if (i < IN_DIM / 32 - 1) {
            const int off = (i + 1) * 32;
            #pragma unroll
            for (int j = 0; j < 4; j++) xa[j] = *(const float4*)(xp + off + j * 4);
            wbh[0] = *(const uint4*)(wph + off); wbh[1] = *(const uint4*)(wph + off + 8);
            wbl[0] = *(const uint4*)(wpl + off); wbl[1] = *(const uint4*)(wpl + off + 8);
        }

        #pragma unroll
        for (int ks = 0; ks < 2; ks++) {
            uint32_t ah[4][4], al[4][4], bh[4][2], bl[4][2];
            const uint32_t akb = (uint32_t)(ks * 32 + (lane >> 4) * 16 + (lane & 15) * SROW);
            #pragma unroll
            for (int im = 0; im < 4; im++) {
                const uint32_t mo = (uint32_t)((wm * 64 + im * 16) * SROW) + akb;
                ldsm_x4(ah[im], uAh + mo);
                ldsm_x4(al[im], uAl + mo);
            }
            const uint32_t bkb = (uint32_t)(ks * 32 + ((lane >> 3) & 1) * 16 + (lane & 7) * SROW);
            #pragma unroll
            for (int in = 0; in < 4; in++) {
                const uint32_t no = (uint32_t)((wn * 32 + in * 8) * SROW) + bkb;
                ldsm_x2(bh[in], uBh + no);
                ldsm_x2(bl[in], uBl + no);
            }
            #pragma unroll
            for (int im = 0; im < 4; im++)
                #pragma unroll
                for (int in = 0; in < 4; in++) {
                    mma16816(acc[im][in], ah[im], bh[in]);
                    mma16816(acc[im][in], ah[im], bl[in]);
                    mma16816(acc[im][in], al[im], bh[in]);
                }
        }
        __syncthreads();
    }

    // epilogue: bias + relu -> g_h1
    #pragma unroll
    for (int im = 0; im < 4; im++) {
        const int rowa = row0 + wm * 64 + im * 16 + (lane >> 2);
        #pragma unroll
        for (int in = 0; in < 4; in++) {
            const int col = wn * 32 + in * 8 + 2 * (lane & 3);
            const float bb0 = b1[col], bb1 = b1[col + 1];
            float2 v0 = make_float2(fmaxf(acc[im][in][0] + bb0, 0.f),
                                    fmaxf(acc[im][in][1] + bb1, 0.f));
            float2 v1 = make_float2(fmaxf(acc[im][in][2] + bb0, 0.f),
                                    fmaxf(acc[im][in][3] + bb1, 0.f));
            *(float2*)&g_h1[(size_t)rowa * H1D + col]       = v0;
            *(float2*)&g_h1[(size_t)(rowa + 8) * H1D + col] = v1;
        }
    }
}

// ---------------------------------------------------------------------------
// Head v3: j-across-lanes layout.
// Block = 256 threads, 64 rows.
// Stage 1: thread (j = tid&63, rg = tid>>6) computes h2[rg*16 + 0..15][j]:
//   one coalesced LDG of W2[k][j] per k (amortized over 16 rows),
//   h1 read from smem via warp-broadcast.
// Stage 2: thread (j2 = tid&31, rg2 = tid>>5) computes z[rg2*8 + 0..7][j2].
// ---------------------------------------------------------------------------
__global__ __launch_bounds__(256) void k_head(const float* __restrict__ W2,
                                              const float* __restrict__ b2,
                                              const float* __restrict__ W3,
                                              const float* __restrict__ b3,
                                              const float* __restrict__ qparams)
{
    __shared__ float h1s[64][132];   // row stride 132 floats (528 B, 16B-aligned)
    __shared__ float h2s[64][68];

    const int row0 = blockIdx.x * 64;
    const int tid  = threadIdx.x;

    // stage h1 tile (64 x 128): 2048 float4, 8 per thread
    #pragma unroll
    for (int i = 0; i < 8; i++) {
        const int f = tid + 256 * i;
        const int r = f >> 5, c4 = (f & 31) << 2;
        *(float4*)&h1s[r][c4] = *(const float4*)&g_h1[(size_t)(row0 + r) * H1D + c4];
    }
    __syncthreads();

    // ---- stage 1: h2 = relu(h1 @ W2 + b2) ----
    {
        const int j  = tid & 63;
        const int rg = tid >> 6;              // 0..3 -> rows rg*16 .. +16
        float acc[16];
        const float bj = b2[j];
        #pragma unroll
        for (int t = 0; t < 16; t++) acc[t] = bj;

        #pragma unroll 4
        for (int k = 0; k < H1D; k++) {
            const float w = W2[k * H2D + j];
            #pragma unroll
            for (int t = 0; t < 16; t++)
                acc[t] = fmaf(h1s[rg * 16 + t][k], w, acc[t]);
        }
        #pragma unroll
        for (int t = 0; t < 16; t++)
            h2s[rg * 16 + t][j] = fmaxf(acc[t], 0.f);
    }
    __syncthreads();

    // ---- stage 2: z = h2 @ W3 + b3 ; q = cos(z + off) ----
    {
        const int j2  = tid & 31;
        const int rg2 = tid >> 5;             // 0..7 -> rows rg2*8 .. +8
        float base = b3[j2];
        #pragma unroll
        for (int rep = 0; rep < 2 * NREPS; rep++)
            base += qparams[rep * LAT + j2];

        float z[8];
        #pragma unroll
        for (int t = 0; t < 8; t++) z[t] = base;

        #pragma unroll 4
        for (int k = 0; k < H2D; k++) {
            const float w = W3[k * LAT + j2];
            #pragma unroll
            for (int t = 0; t < 8; t++)
                z[t] = fmaf(h2s[rg2 * 8 + t][k], w, z[t]);
        }

        #pragma unroll
        for (int t = 0; t < 8; t++) {
            const int row = row0 + rg2 * 8 + t;
            const float qv = cosf(z[t]);
            __nv_bfloat16 hh, ll;
            split_bf16(qv, hh, ll);
            g_q_h[(size_t)row * LAT + j2] = hh;
            g_q_l[(size_t)row * LAT + j2] = ll;
        }
    }
}

// ---------------------------------------------------------------------------
// GEMM2 (mma.sync): out = q @ Wd + bd.  CTA tile 128x128, K=32 single shot.
// ---------------------------------------------------------------------------
__global__ __launch_bounds__(256) void k_gemm2_mma(const float* __restrict__ bd,
                                                   float* __restrict__ out)
{
    __shared__ __align__(128) char sm[4 * 128 * SROW];
    char* sQh = sm;
    char* sQl = sm + 128 * SROW;
    char* sWh = sm + 2 * 128 * SROW;
    char* sWl = sm + 3 * 128 * SROW;
    const uint32_t uQh = smem_u32(sQh), uQl = smem_u32(sQl);
    const uint32_t uWh = smem_u32(sWh), uWl = smem_u32(sWl);

    const int tid  = threadIdx.x;
    const int lane = tid & 31, wid = tid >> 5;
    const int wm = wid >> 2, wn = wid & 3;
    const int r = tid >> 1, h = tid & 1;
    const int n0 = blockIdx.x * 128;
    const int m0 = blockIdx.y * 128;

    const uint32_t sts = (uint32_t)(r * SROW + h * 32);
    {
        const __nv_bfloat16* qh = &g_q_h[(size_t)(m0 + r) * LAT + h * 16];
        const __nv_bfloat16* ql = &g_q_l[(size_t)(m0 + r) * LAT + h * 16];
        const __nv_bfloat16* wh = &g_Wdt_h[(size_t)(n0 + r) * LAT + h * 16];
        const __nv_bfloat16* wl = &g_Wdt_l[(size_t)(n0 + r) * LAT + h * 16];
        *(uint4*)(sQh + sts)      = *(const uint4*)qh;
        *(uint4*)(sQh + sts + 16) = *(const uint4*)(qh + 8);
        *(uint4*)(sQl + sts)      = *(const uint4*)ql;
        *(uint4*)(sQl + sts + 16) = *(const uint4*)(ql + 8);
        *(uint4*)(sWh + sts)      = *(const uint4*)wh;
        *(uint4*)(sWh + sts + 16) = *(const uint4*)(wh + 8);
        *(uint4*)(sWl + sts)      = *(const uint4*)wl;
        *(uint4*)(sWl + sts + 16) = *(const uint4*)(wl + 8);
    }
    __syncthreads();

    float acc[4][4][4];
    #pragma unroll
    for (int im = 0; im < 4; im++)
        #pragma unroll
        for (int in = 0; in < 4; in++)
            #pragma unroll
            for (int j = 0; j < 4; j++) acc[im][in][j] = 0.f;

    #pragma unroll
    for (int ks = 0; ks < 2; ks++) {
        uint32_t ah[4][4], al[4][4], bh[4][2], bl[4][2];
        const uint32_t akb = (uint32_t)(ks * 32 + (lane >> 4) * 16 + (lane & 15) * SROW);
        #pragma unroll
        for (int im = 0; im < 4; im++) {
            const uint32_t mo = (uint32_t)((wm * 64 + im * 16) * SROW) + akb;
            ldsm_x4(ah[im], uQh + mo);
            ldsm_x4(al[im], uQl + mo);
        }
        const uint32_t bkb = (uint32_t)(ks * 32 + ((lane >> 3) & 1) * 16 + (lane & 7) * SROW);
        #pragma unroll
        for (int in = 0; in < 4; in++) {
            const uint32_t no = (uint32_t)((wn * 32 + in * 8) * SROW) + bkb;
            ldsm_x2(bh[in], uWh + no);
            ldsm_x2(bl[in], uWl + no);
        }
        #pragma unroll
        for (int im = 0; im < 4; im++)
            #pragma unroll
            for (int in = 0; in < 4; in++) {
                mma16816(acc[im][in], ah[im], bh[in]);
                mma16816(acc[im][in], ah[im], bl[in]);
                mma16816(acc[im][in], al[im], bh[in]);
            }
    }

    // epilogue: + bd -> out
    #pragma unroll
    for (int im = 0; im < 4; im++) {
        const int rowa = m0 + wm * 64 + im * 16 + (lane >> 2);
        #pragma unroll
        for (int in = 0; in < 4; in++) {
            const int col = n0 + wn * 32 + in * 8 + 2 * (lane & 3);
            const float bb0 = bd[col], bb1 = bd[col + 1];
            float2 v0 = make_float2(acc[im][in][0] + bb0, acc[im][in][1] + bb1);
            float2 v1 = make_float2(acc[im][in][2] + bb0, acc[im][in][3] + bb1);
            *(float2*)&out[(size_t)rowa * IN_DIM + col]       = v0;
            *(float2*)&out[(size_t)(rowa + 8) * IN_DIM + col] = v1;
        }
    }
}

// ---------------------------------------------------------------------------
extern "C" void kernel_launch(void* const* d_in, const int* in_sizes, int n_in,
                              void* d_out, int out_size)
{
    const float* x  = (const float*)d_in[0];
    const float* W1 = (const float*)d_in[1];
    const float* b1 = (const float*)d_in[2];
    const float* W2 = (const float*)d_in[3];
    const float* b2 = (const float*)d_in[4];
    const float* W3 = (const float*)d_in[5];
    const float* b3 = (const float*)d_in[6];
    const float* qp = (const float*)d_in[7];
    const float* Wd = (const float*)d_in[8];
    const float* bd = (const float*)d_in[9];
    float* out = (float*)d_out;

    k_tr_W1<<<dim3(IN_DIM / 32, H1D / 32), dim3(32, 8)>>>(W1);
    k_tr_Wd<<<IN_DIM / 32, dim3(32, 8)>>>(Wd);
    k_gemm1_mma<<<BDIM / 128, 256>>>(x, b1);
    k_head<<<BDIM / 64, 256>>>(W2, b2, W3, b3, qp);
    k_gemm2_mma<<<dim3(IN_DIM / 128, BDIM / 128), 256>>>(bd, out);
}